// round 1
// baseline (speedup 1.0000x reference)
#include <cuda_runtime.h>

// QuantumLayer collapses analytically:
//   theta = x @ W_in^T + b_in                       (256 x 16)
//   e[b,q] = prod_{j in S_q} cos(theta[b,j])        S_q = { j<=q : (q-j) mod 4 in {0,1} }
//   out = e @ W_out^T + b_out                       (256 x 128)
// RZ phases (q_weights) are unit-modulus diagonals and CNOTs are basis
// permutations, so they cannot change measurement probabilities beyond the
// permutation Q^3; Q^{-3} = T^3 (prefix-XOR cubed) gives the masks below.

__constant__ unsigned short c_masks[16] = {
    0x0001, 0x0003, 0x0006, 0x000C,
    0x0019, 0x0033, 0x0066, 0x00CC,
    0x0199, 0x0333, 0x0666, 0x0CCC,
    0x1999, 0x3333, 0x6666, 0xCCCC
};

__global__ void __launch_bounds__(128) quantum_layer_kernel(
    const float* __restrict__ x,      // (256, 128)
    const float* __restrict__ W_in,   // (16, 128)
    const float* __restrict__ b_in,   // (16)
    const float* __restrict__ W_out,  // (128, 16)
    const float* __restrict__ b_out,  // (128)
    float* __restrict__ out)          // (256, 128)
{
    __shared__ float xs[128];
    __shared__ float cs[16];   // cos(theta[b, q])
    __shared__ float e[16];    // expvals

    const int b    = blockIdx.x;
    const int t    = threadIdx.x;
    const int warp = t >> 5;
    const int lane = t & 31;

    xs[t] = x[b * 128 + t];
    __syncthreads();

    // Each of the 4 warps computes 4 of the 16 dot products theta[b,q].
    #pragma unroll
    for (int i = 0; i < 4; ++i) {
        const int q = warp * 4 + i;
        const float* w = W_in + q * 128;
        float p = xs[lane]      * w[lane]
                + xs[lane + 32] * w[lane + 32]
                + xs[lane + 64] * w[lane + 64]
                + xs[lane + 96] * w[lane + 96];
        #pragma unroll
        for (int o = 16; o > 0; o >>= 1)
            p += __shfl_down_sync(0xffffffffu, p, o);
        if (lane == 0)
            cs[q] = cosf(p + b_in[q]);
    }
    __syncthreads();

    // expvals: masked product of cosines.
    if (t < 16) {
        const unsigned m = c_masks[t];
        float prod = 1.0f;
        #pragma unroll
        for (int j = 0; j < 16; ++j)
            if ((m >> j) & 1u) prod *= cs[j];
        e[t] = prod;
    }
    __syncthreads();

    // out[b, t] = sum_q e[q] * W_out[t, q] + b_out[t]
    float acc = b_out[t];
    const float* wo = W_out + t * 16;
    #pragma unroll
    for (int q = 0; q < 16; ++q)
        acc = fmaf(e[q], wo[q], acc);
    out[b * 128 + t] = acc;
}

extern "C" void kernel_launch(void* const* d_in, const int* in_sizes, int n_in,
                              void* d_out, int out_size) {
    const float* x     = (const float*)d_in[0];  // (256,128)
    const float* W_in  = (const float*)d_in[1];  // (16,128)
    const float* b_in  = (const float*)d_in[2];  // (16)
    // d_in[3] = q_weights (3,16) — provably no effect on output, unused.
    const float* W_out = (const float*)d_in[4];  // (128,16)
    const float* b_out = (const float*)d_in[5];  // (128)
    float* out = (float*)d_out;                  // (256,128)

    quantum_layer_kernel<<<256, 128>>>(x, W_in, b_in, W_out, b_out, out);
}

// round 2
// speedup vs baseline: 1.3077x; 1.3077x over previous
#include <cuda_runtime.h>

// Analytic collapse of the 16-qubit circuit (see R1):
//   theta = x @ W_in^T + b_in
//   e[b,q] = prod_{j in mask_q} cos(theta[b,j])
//   out    = e @ W_out^T + b_out
// q_weights (RZ phases) provably cannot affect measured probabilities.

__constant__ unsigned short c_masks[16] = {
    0x0001, 0x0003, 0x0006, 0x000C,
    0x0019, 0x0033, 0x0066, 0x00CC,
    0x0199, 0x0333, 0x0666, 0x0CCC,
    0x1999, 0x3333, 0x6666, 0xCCCC
};

__global__ void __launch_bounds__(128) quantum_layer_kernel(
    const float4* __restrict__ x4,    // (256, 32) float4
    const float4* __restrict__ Wi4,   // (16, 32)  float4
    const float*  __restrict__ b_in,  // (16)
    const float4* __restrict__ Wo4,   // (128, 4)  float4
    const float*  __restrict__ b_out, // (128)
    float* __restrict__ out)          // (256, 128)
{
    __shared__ float cs[16];  // cos(theta[b,q])
    __shared__ float e[16];   // expvals

    const int b = blockIdx.x;
    const int t = threadIdx.x;
    const int q = t >> 3;     // 16 q's, one per 8-lane group (groups within a warp)
    const int g = t & 7;      // position within group

    // ---- Hoist all loads that are only needed AFTER the syncs: their latency
    // hides under the dot-product phase. ----
    const float4* wo = Wo4 + t * 4;
    const float4  w0 = wo[0], w1 = wo[1], w2 = wo[2], w3 = wo[3];
    const float   bo = b_out[t];
    const unsigned m = (t < 16) ? (unsigned)c_masks[t] : 0u;
    const float   bq = b_in[q];   // broadcast within each 8-lane group

    // ---- theta[b,q]: 8 lanes x 16 elements, 4x LDG.128 each, all 16 q's
    // concurrent across the block. ----
    float p0 = 0.f, p1 = 0.f;
    #pragma unroll
    for (int kk = 0; kk < 4; kk += 2) {
        float4 xa = x4[b * 32 + g * 4 + kk];
        float4 wa = Wi4[q * 32 + g * 4 + kk];
        float4 xb = x4[b * 32 + g * 4 + kk + 1];
        float4 wb = Wi4[q * 32 + g * 4 + kk + 1];
        p0 += xa.x * wa.x + xa.y * wa.y + xa.z * wa.z + xa.w * wa.w;
        p1 += xb.x * wb.x + xb.y * wb.y + xb.z * wb.z + xb.w * wb.w;
    }
    float p = p0 + p1;
    p += __shfl_down_sync(0xffffffffu, p, 4, 8);
    p += __shfl_down_sync(0xffffffffu, p, 2, 8);
    p += __shfl_down_sync(0xffffffffu, p, 1, 8);
    if (g == 0) cs[q] = __cosf(p + bq);   // MUFU, |theta| small, tol 1e-3
    __syncthreads();

    // ---- expvals: masked products of the 16 cosines. ----
    if (t < 16) {
        float prod = 1.0f;
        #pragma unroll
        for (int j = 0; j < 16; ++j)
            if ((m >> j) & 1u) prod *= cs[j];
        e[t] = prod;
    }
    __syncthreads();

    // ---- out[b,t] = b_out[t] + sum_q e[q] * W_out[t,q]  (weights preloaded) ----
    float acc = bo;
    acc += e[0]  * w0.x + e[1]  * w0.y + e[2]  * w0.z + e[3]  * w0.w;
    acc += e[4]  * w1.x + e[5]  * w1.y + e[6]  * w1.z + e[7]  * w1.w;
    acc += e[8]  * w2.x + e[9]  * w2.y + e[10] * w2.z + e[11] * w2.w;
    acc += e[12] * w3.x + e[13] * w3.y + e[14] * w3.z + e[15] * w3.w;
    out[b * 128 + t] = acc;
}

extern "C" void kernel_launch(void* const* d_in, const int* in_sizes, int n_in,
                              void* d_out, int out_size) {
    const float4* x4    = (const float4*)d_in[0];  // (256,128)
    const float4* Wi4   = (const float4*)d_in[1];  // (16,128)
    const float*  b_in  = (const float*)d_in[2];   // (16)
    // d_in[3] = q_weights — provably no effect on output.
    const float4* Wo4   = (const float4*)d_in[4];  // (128,16)
    const float*  b_out = (const float*)d_in[5];   // (128)
    float* out = (float*)d_out;

    quantum_layer_kernel<<<256, 128>>>(x4, Wi4, b_in, Wo4, b_out, out);
}